// round 4
// baseline (speedup 1.0000x reference)
#include <cuda_runtime.h>
#include <cuda_bf16.h>
#include <cstdint>

#define B_    4
#define NB_   64
#define T_    512
#define C_    256
#define H_    8
#define HD_   32
#define L_    64
#define NWIN  2048
#define SCALE_ 0.17677669529663687f
#define EPS_  1e-5f

// padded strides (bf16 elements). 264*2=528B -> bank offset 4 per row.
#define XS    264
// 72*2=144B -> bank offset 4 per row.
#define WS    72
#define VS    72

// ---- shared memory layout (bytes) ----
#define X_OFF     0                        // 64 x XS bf16 (LN out; reused for O)
#define Q_OFF     (X_OFF + 64*XS*2)        // 33792
#define K_OFF     (Q_OFF + 64*XS*2)        // 67584
#define VT_OFF    (K_OFF + 64*XS*2)        // 101376 : 256 x VS bf16 (V transposed)
#define W0_OFF    (VT_OFF + 256*VS*2)      // 138240 : 256 x WS bf16 weight k-tile buf0
#define W1_OFF    (W0_OFF + 256*WS*2)      // 175104 : buf1
#define BIAS_OFF  (W1_OFF + 256*WS*2)      // 211968 : 4x256 f32
#define G_OFF     (BIAS_OFF + 4096)
#define BETA_OFF  (G_OFF + 1024)
#define ADDR_OFF  (BETA_OFF + 1024)
#define SMEM_TOTAL (ADDR_OFF + 256)        // 218368

__device__ __nv_bfloat16 g_wq[65536];
__device__ __nv_bfloat16 g_wk[65536];
__device__ __nv_bfloat16 g_wv[65536];
__device__ __nv_bfloat16 g_wp[65536];

__global__ void cvt_kernel(const float* __restrict__ wq, const float* __restrict__ wk,
                           const float* __restrict__ wv, const float* __restrict__ wp) {
    int i = blockIdx.x * blockDim.x + threadIdx.x;   // 65536 threads exactly
    g_wq[i] = __float2bfloat16(wq[i]);
    g_wk[i] = __float2bfloat16(wk[i]);
    g_wv[i] = __float2bfloat16(wv[i]);
    g_wp[i] = __float2bfloat16(wp[i]);
}

__device__ __forceinline__ void mma16816(float c[4], const uint32_t a[4], uint32_t b0, uint32_t b1) {
    asm volatile(
        "mma.sync.aligned.m16n8k16.row.col.f32.bf16.bf16.f32 "
        "{%0,%1,%2,%3}, {%4,%5,%6,%7}, {%8,%9}, {%0,%1,%2,%3};\n"
        : "+f"(c[0]), "+f"(c[1]), "+f"(c[2]), "+f"(c[3])
        : "r"(a[0]), "r"(a[1]), "r"(a[2]), "r"(a[3]), "r"(b0), "r"(b1));
}

__device__ __forceinline__ uint32_t pack_bf16(float lo, float hi) {
    __nv_bfloat162 h = __floats2bfloat162_rn(lo, hi);
    return *reinterpret_cast<uint32_t*>(&h);
}

// issue one 64-wide k-tile (256n x 64k bf16 = 32KB) of Wg into smem buffer via cp.async
__device__ __forceinline__ void issue_wtile(const __nv_bfloat16* __restrict__ Wg,
                                            uint32_t buf_s, int kt, int tid) {
    #pragma unroll
    for (int k2 = 0; k2 < 8; ++k2) {
        int idx = tid + k2 * 256;          // 2048 x 16B
        int n = idx >> 3, j = idx & 7;
        uint32_t dst = buf_s + n * (WS * 2) + j * 16;
        const char* src = (const char*)Wg + n * 512 + kt * 128 + j * 16;
        asm volatile("cp.async.cg.shared.global [%0], [%1], 16;\n" :: "r"(dst), "l"(src));
    }
    asm volatile("cp.async.commit_group;\n" ::: "memory");
}

// GEMM: out(64x256) = A(64x256 smem bf16, row stride XS) @ Wg^T, Wg gmem bf16 [n][k].
// Double-buffered cp.async weight streaming; warp grid 2x4 (m0 = warpM*32, n0 = warpN*64).
__device__ __forceinline__ void gemm_64x256(
    const __nv_bfloat16* __restrict__ A, const __nv_bfloat16* __restrict__ Wg,
    __nv_bfloat16* sW0, __nv_bfloat16* sW1, float acc[2][8][4],
    int tid, int m0, int n0, int g, int t4)
{
    uint32_t s0 = (uint32_t)__cvta_generic_to_shared(sW0);
    uint32_t s1 = (uint32_t)__cvta_generic_to_shared(sW1);

    issue_wtile(Wg, s0, 0, tid);

    #pragma unroll
    for (int kt = 0; kt < 4; ++kt) {
        asm volatile("cp.async.wait_group 0;\n" ::: "memory");
        __syncthreads();   // tile kt visible; all threads done with compute(kt-1)
        if (kt < 3) issue_wtile(Wg, (kt & 1) ? s0 : s1, kt + 1, tid);
        const __nv_bfloat16* sW = (kt & 1) ? sW1 : sW0;

        #pragma unroll
        for (int ks = 0; ks < 4; ++ks) {
            int kc = kt * 64 + ks * 16 + t4 * 2;
            uint32_t a[2][4];
            #pragma unroll
            for (int mi = 0; mi < 2; ++mi) {
                int r = m0 + mi * 16 + g;
                a[mi][0] = *(const uint32_t*)(A + r * XS + kc);
                a[mi][1] = *(const uint32_t*)(A + (r + 8) * XS + kc);
                a[mi][2] = *(const uint32_t*)(A + r * XS + kc + 8);
                a[mi][3] = *(const uint32_t*)(A + (r + 8) * XS + kc + 8);
            }
            #pragma unroll
            for (int ni = 0; ni < 8; ++ni) {
                int n = n0 + ni * 8 + g;
                int kk = ks * 16 + t4 * 2;
                uint32_t b0 = *(const uint32_t*)(sW + n * WS + kk);
                uint32_t b1 = *(const uint32_t*)(sW + n * WS + kk + 8);
                mma16816(acc[0][ni], a[0], b0, b1);
                mma16816(acc[1][ni], a[1], b0, b1);
            }
        }
    }
}

__global__ void __launch_bounds__(256, 1)
win_kernel(const float* __restrict__ inpt,
           const int* __restrict__ perm_n, const int* __restrict__ perm_t,
           const float* __restrict__ ln_g, const float* __restrict__ ln_b,
           const float* __restrict__ bq, const float* __restrict__ bk,
           const float* __restrict__ bv, const float* __restrict__ bp,
           float* __restrict__ out)
{
    extern __shared__ char smem[];
    __nv_bfloat16* sX  = (__nv_bfloat16*)(smem + X_OFF);
    __nv_bfloat16* sQ  = (__nv_bfloat16*)(smem + Q_OFF);
    __nv_bfloat16* sK  = (__nv_bfloat16*)(smem + K_OFF);
    __nv_bfloat16* sVt = (__nv_bfloat16*)(smem + VT_OFF);
    __nv_bfloat16* sW0 = (__nv_bfloat16*)(smem + W0_OFF);
    __nv_bfloat16* sW1 = (__nv_bfloat16*)(smem + W1_OFF);
    float* sBias = (float*)(smem + BIAS_OFF);
    float* sG    = (float*)(smem + G_OFF);
    float* sBt   = (float*)(smem + BETA_OFF);
    int*   sAddr = (int*)(smem + ADDR_OFF);

    int tid = threadIdx.x;
    int w = blockIdx.x;
    int tbi = w & 63, nbi = (w >> 6) & 7, b = w >> 9;

    // ---- stage constants + gather/scatter addresses ----
    sBias[tid]       = bq[tid];
    sBias[256 + tid] = bk[tid];
    sBias[512 + tid] = bv[tid];
    sBias[768 + tid] = bp[tid];
    sG[tid]  = ln_g[tid];
    sBt[tid] = ln_b[tid];
    if (tid < 64) {
        int fw = tid >> 3, tw = tid & 7;
        int pn = perm_n[b * NB_ + nbi * 8 + fw];
        int pt = perm_t[b * T_ + tbi * 8 + tw];
        sAddr[tid] = ((b * NB_ + pn) * T_ + pt) * C_;
    }
    __syncthreads();

    int warp = tid >> 5, lane = tid & 31;
    int g = lane >> 2, t4 = lane & 3;

    // ---- Phase 1: gather + LayerNorm -> sX (bf16) ----
    #pragma unroll
    for (int it = 0; it < 8; ++it) {
        int l = warp * 8 + it;
        const float4* row = (const float4*)(inpt + sAddr[l]);
        float4 v0 = row[lane];
        float4 v1 = row[lane + 32];
        float s  = v0.x + v0.y + v0.z + v0.w + v1.x + v1.y + v1.z + v1.w;
        float sq = v0.x*v0.x + v0.y*v0.y + v0.z*v0.z + v0.w*v0.w
                 + v1.x*v1.x + v1.y*v1.y + v1.z*v1.z + v1.w*v1.w;
        #pragma unroll
        for (int o = 16; o; o >>= 1) {
            s  += __shfl_xor_sync(0xffffffffu, s, o);
            sq += __shfl_xor_sync(0xffffffffu, sq, o);
        }
        float mean = s * (1.0f / 256.0f);
        float var  = sq * (1.0f / 256.0f) - mean * mean;
        float rstd = rsqrtf(var + EPS_);
        int c0 = lane * 4, c1 = (lane + 32) * 4;
        uint32_t* xr = (uint32_t*)(sX + l * XS);
        float a0 = (v0.x - mean) * rstd * sG[c0]     + sBt[c0];
        float a1 = (v0.y - mean) * rstd * sG[c0 + 1] + sBt[c0 + 1];
        float a2 = (v0.z - mean) * rstd * sG[c0 + 2] + sBt[c0 + 2];
        float a3 = (v0.w - mean) * rstd * sG[c0 + 3] + sBt[c0 + 3];
        float b0v = (v1.x - mean) * rstd * sG[c1]     + sBt[c1];
        float b1v = (v1.y - mean) * rstd * sG[c1 + 1] + sBt[c1 + 1];
        float b2v = (v1.z - mean) * rstd * sG[c1 + 2] + sBt[c1 + 2];
        float b3v = (v1.w - mean) * rstd * sG[c1 + 3] + sBt[c1 + 3];
        xr[(c0 >> 1)]     = pack_bf16(a0, a1);
        xr[(c0 >> 1) + 1] = pack_bf16(a2, a3);
        xr[(c1 >> 1)]     = pack_bf16(b0v, b1v);
        xr[(c1 >> 1) + 1] = pack_bf16(b2v, b3v);
    }

    int wm = warp >> 2, wn = warp & 3;
    int m0 = wm * 32, n0 = wn * 64;

    // ---- Phase 2: QKV projections ----
    for (int ws = 0; ws < 3; ++ws) {
        const __nv_bfloat16* Wg = (ws == 0) ? g_wq : (ws == 1) ? g_wk : g_wv;
        float acc[2][8][4];
        #pragma unroll
        for (int mi = 0; mi < 2; ++mi)
            #pragma unroll
            for (int ni = 0; ni < 8; ++ni)
                #pragma unroll
                for (int j = 0; j < 4; ++j) acc[mi][ni][j] = 0.f;

        gemm_64x256(sX, Wg, sW0, sW1, acc, tid, m0, n0, g, t4);

        #pragma unroll
        for (int mi = 0; mi < 2; ++mi)
        #pragma unroll
        for (int ni = 0; ni < 8; ++ni) {
            int r = m0 + mi * 16 + g, r2 = r + 8;
            int cn = n0 + ni * 8 + t4 * 2;
            float bb0 = sBias[ws * 256 + cn], bb1 = sBias[ws * 256 + cn + 1];
            float v0 = acc[mi][ni][0] + bb0;
            float v1 = acc[mi][ni][1] + bb1;
            float v2 = acc[mi][ni][2] + bb0;
            float v3 = acc[mi][ni][3] + bb1;
            if (ws == 0) {
                v0 *= SCALE_; v1 *= SCALE_; v2 *= SCALE_; v3 *= SCALE_;
                *(uint32_t*)(sQ + r * XS + cn)  = pack_bf16(v0, v1);
                *(uint32_t*)(sQ + r2 * XS + cn) = pack_bf16(v2, v3);
            } else if (ws == 1) {
                *(uint32_t*)(sK + r * XS + cn)  = pack_bf16(v0, v1);
                *(uint32_t*)(sK + r2 * XS + cn) = pack_bf16(v2, v3);
            } else {
                sVt[cn * VS + r]        = __float2bfloat16(v0);
                sVt[(cn + 1) * VS + r]  = __float2bfloat16(v1);
                sVt[cn * VS + r2]       = __float2bfloat16(v2);
                sVt[(cn + 1) * VS + r2] = __float2bfloat16(v3);
            }
        }
    }
    __syncthreads();   // Q/K/Vt fully materialized

    // ---- Phase 3: attention, one head per warp, two 32-row halves ----
    {
        int h = warp;
        #pragma unroll
        for (int mh = 0; mh < 2; ++mh) {
            float s[2][8][4];
            #pragma unroll
            for (int mi = 0; mi < 2; ++mi)
                #pragma unroll
                for (int ni = 0; ni < 8; ++ni)
                    #pragma unroll
                    for (int j = 0; j < 4; ++j) s[mi][ni][j] = 0.f;

            #pragma unroll
            for (int ks = 0; ks < 2; ++ks) {
                int kc = h * 32 + ks * 16 + t4 * 2;
                uint32_t a[2][4];
                #pragma unroll
                for (int mi = 0; mi < 2; ++mi) {
                    int r = mh * 32 + mi * 16 + g;
                    a[mi][0] = *(const uint32_t*)(sQ + r * XS + kc);
                    a[mi][1] = *(const uint32_t*)(sQ + (r + 8) * XS + kc);
                    a[mi][2] = *(const uint32_t*)(sQ + r * XS + kc + 8);
                    a[mi][3] = *(const uint32_t*)(sQ + (r + 8) * XS + kc + 8);
                }
                #pragma unroll
                for (int ni = 0; ni < 8; ++ni) {
                    int ntok = ni * 8 + g;
                    uint32_t b0 = *(const uint32_t*)(sK + ntok * XS + kc);
                    uint32_t b1 = *(const uint32_t*)(sK + ntok * XS + kc + 8);
                    #pragma unroll
                    for (int mi = 0; mi < 2; ++mi) mma16816(s[mi][ni], a[mi], b0, b1);
                }
            }

            // softmax over 64 cols per row (4 threads of a quad share each row)
            #pragma unroll
            for (int mi = 0; mi < 2; ++mi)
            #pragma unroll
            for (int hf = 0; hf < 2; ++hf) {
                float m = -1e30f;
                #pragma unroll
                for (int ni = 0; ni < 8; ++ni)
                    m = fmaxf(m, fmaxf(s[mi][ni][hf * 2], s[mi][ni][hf * 2 + 1]));
                m = fmaxf(m, __shfl_xor_sync(0xffffffffu, m, 1));
                m = fmaxf(m, __shfl_xor_sync(0xffffffffu, m, 2));
                float sum = 0.f;
                #pragma unroll
                for (int ni = 0; ni < 8; ++ni) {
                    float e0 = __expf(s[mi][ni][hf * 2]     - m);
                    float e1 = __expf(s[mi][ni][hf * 2 + 1] - m);
                    s[mi][ni][hf * 2] = e0; s[mi][ni][hf * 2 + 1] = e1;
                    sum += e0 + e1;
                }
                sum += __shfl_xor_sync(0xffffffffu, sum, 1);
                sum += __shfl_xor_sync(0xffffffffu, sum, 2);
                float inv = 1.0f / sum;
                #pragma unroll
                for (int ni = 0; ni < 8; ++ni) {
                    s[mi][ni][hf * 2] *= inv; s[mi][ni][hf * 2 + 1] *= inv;
                }
            }

            // convert P (C-frags) -> A-frags for O = P @ V
            uint32_t pA[2][4][4];
            #pragma unroll
            for (int mi = 0; mi < 2; ++mi)
            #pragma unroll
            for (int kt2 = 0; kt2 < 4; ++kt2) {
                pA[mi][kt2][0] = pack_bf16(s[mi][2 * kt2][0],     s[mi][2 * kt2][1]);
                pA[mi][kt2][1] = pack_bf16(s[mi][2 * kt2][2],     s[mi][2 * kt2][3]);
                pA[mi][kt2][2] = pack_bf16(s[mi][2 * kt2 + 1][0], s[mi][2 * kt2 + 1][1]);
                pA[mi][kt2][3] = pack_bf16(s[mi][2 * kt2 + 1][2], s[mi][2 * kt2 + 1][3]);
            }

            float o[2][4][4];
            #pragma unroll
            for (int mi = 0; mi < 2; ++mi)
                #pragma unroll
                for (int ni2 = 0; ni2 < 4; ++ni2)
                    #pragma unroll
                    for (int j = 0; j < 4; ++j) o[mi][ni2][j] = 0.f;

            #pragma unroll
            for (int kt2 = 0; kt2 < 4; ++kt2)
            #pragma unroll
            for (int ni2 = 0; ni2 < 4; ++ni2) {
                int d = h * 32 + ni2 * 8 + g;
                uint32_t b0 = *(const uint32_t*)(sVt + d * VS + kt2 * 16 + t4 * 2);
                uint32_t b1 = *(const uint32_t*)(sVt + d * VS + kt2 * 16 + t4 * 2 + 8);
                #pragma unroll
                for (int mi = 0; mi < 2; ++mi) mma16816(o[mi][ni2], pA[mi][kt2], b0, b1);
            }

            // write O (head h -> cols h*32..) into sX (X no longer needed)
            #pragma unroll
            for (int mi = 0; mi < 2; ++mi)
            #pragma unroll
            for (int ni2 = 0; ni2 < 4; ++ni2) {
                int r = mh * 32 + mi * 16 + g;
                int cn = h * 32 + ni2 * 8 + t4 * 2;
                *(uint32_t*)(sX + r * XS + cn)       = pack_bf16(o[mi][ni2][0], o[mi][ni2][1]);
                *(uint32_t*)(sX + (r + 8) * XS + cn) = pack_bf16(o[mi][ni2][2], o[mi][ni2][3]);
            }
        }
    }
    // (barrier inside gemm_64x256 iter0 orders O writes before proj A-reads)

    // ---- Phase 4: output projection + residual + scatter ----
    {
        float acc[2][8][4];
        #pragma unroll
        for (int mi = 0; mi < 2; ++mi)
            #pragma unroll
            for (int ni = 0; ni < 8; ++ni)
                #pragma unroll
                for (int j = 0; j < 4; ++j) acc[mi][ni][j] = 0.f;

        gemm_64x256(sX, g_wp, sW0, sW1, acc, tid, m0, n0, g, t4);

        #pragma unroll
        for (int mi = 0; mi < 2; ++mi)
        #pragma unroll
        for (int ni = 0; ni < 8; ++ni) {
            int r = m0 + mi * 16 + g, r2 = r + 8;
            int cn = n0 + ni * 8 + t4 * 2;
            float bb0 = sBias[768 + cn], bb1 = sBias[768 + cn + 1];
            int base1 = sAddr[r], base2 = sAddr[r2];
            float2 i0 = *(const float2*)(inpt + base1 + cn);
            float2 i1 = *(const float2*)(inpt + base2 + cn);
            float2 y0, y1;
            y0.x = acc[mi][ni][0] + bb0 + i0.x;
            y0.y = acc[mi][ni][1] + bb1 + i0.y;
            y1.x = acc[mi][ni][2] + bb0 + i1.x;
            y1.y = acc[mi][ni][3] + bb1 + i1.y;
            *(float2*)(out + base1 + cn) = y0;
            *(float2*)(out + base2 + cn) = y1;
        }
    }
}

extern "C" void kernel_launch(void* const* d_in, const int* in_sizes, int n_in,
                              void* d_out, int out_size) {
    const float* inpt   = (const float*)d_in[0];
    const int*   perm_n = (const int*)  d_in[1];
    const int*   perm_t = (const int*)  d_in[2];
    const float* ln_g   = (const float*)d_in[3];
    const float* ln_b   = (const float*)d_in[4];
    const float* Wq     = (const float*)d_in[5];
    const float* bq     = (const float*)d_in[6];
    const float* Wk     = (const float*)d_in[7];
    const float* bk     = (const float*)d_in[8];
    const float* Wv     = (const float*)d_in[9];
    const float* bv     = (const float*)d_in[10];
    const float* Wp     = (const float*)d_in[11];
    const float* bp     = (const float*)d_in[12];
    float* out = (float*)d_out;

    cudaFuncSetAttribute(win_kernel, cudaFuncAttributeMaxDynamicSharedMemorySize, SMEM_TOTAL);

    cvt_kernel<<<256, 256>>>(Wq, Wk, Wv, Wp);
    win_kernel<<<NWIN, 256, SMEM_TOTAL>>>(inpt, perm_n, perm_t, ln_g, ln_b,
                                          bq, bk, bv, bp, out);
}

// round 14
// speedup vs baseline: 1.1365x; 1.1365x over previous
#include <cuda_runtime.h>
#include <cuda_bf16.h>
#include <cstdint>

#define B_    4
#define NB_   64
#define T_    512
#define C_    256
#define NWIN  2048
#define SCALE_ 0.17677669529663687f
#define EPS_  1e-5f

// padded strides (bf16 elems): 264*2=528B -> per-row bank offset 4 (conflict-free frags)
#define XS    264
// private weight slice stride: 72*2=144B -> bank offset 4
#define WS    72
#define PW_STAGE_ELEMS (32 * WS)          // 2304 bf16
#define PW_STAGE_BYTES (PW_STAGE_ELEMS*2) // 4608 B
#define NSTAGE 3

// ---- shared memory layout (bytes) ----
#define X_OFF     0                          // 64 x XS bf16 (LN out)
#define O_OFF     (X_OFF + 64*XS*2)          // 33792 : 64 x XS bf16 (attn out)
#define PW_OFF    (O_OFF + 64*XS*2)          // 67584 : 8 warps x 3 stages x 4608
#define BIAS_OFF  (PW_OFF + 8*NSTAGE*PW_STAGE_BYTES) // 178176 : 4x256 f32
#define G_OFF     (BIAS_OFF + 4096)
#define BETA_OFF  (G_OFF + 1024)
#define ADDR_OFF  (BETA_OFF + 1024)
#define SMEM_TOTAL (ADDR_OFF + 256)          // 184576

__device__ __nv_bfloat16 g_wq[65536];
__device__ __nv_bfloat16 g_wk[65536];
__device__ __nv_bfloat16 g_wv[65536];
__device__ __nv_bfloat16 g_wp[65536];

__global__ void cvt_kernel(const float* __restrict__ wq, const float* __restrict__ wk,
                           const float* __restrict__ wv, const float* __restrict__ wp) {
    int i = blockIdx.x * blockDim.x + threadIdx.x;   // 65536 threads exactly
    g_wq[i] = __float2bfloat16(wq[i]);
    g_wk[i] = __float2bfloat16(wk[i]);
    g_wv[i] = __float2bfloat16(wv[i]);
    g_wp[i] = __float2bfloat16(wp[i]);
}

__device__ __forceinline__ void mma16816(float c[4], const uint32_t a[4], uint32_t b0, uint32_t b1) {
    asm volatile(
        "mma.sync.aligned.m16n8k16.row.col.f32.bf16.bf16.f32 "
        "{%0,%1,%2,%3}, {%4,%5,%6,%7}, {%8,%9}, {%0,%1,%2,%3};\n"
        : "+f"(c[0]), "+f"(c[1]), "+f"(c[2]), "+f"(c[3])
        : "r"(a[0]), "r"(a[1]), "r"(a[2]), "r"(a[3]), "r"(b0), "r"(b1));
}

__device__ __forceinline__ uint32_t pack_bf16(float lo, float hi) {
    __nv_bfloat162 h = __floats2bfloat162_rn(lo, hi);
    return *reinterpret_cast<uint32_t*>(&h);
}

// issue warp-private weight k-tile t (global tile id 0..15; 4 per matrix) via cp.async
__device__ __forceinline__ void issue_tile(int t, int w, uint32_t pw_u32, int lane) {
    const __nv_bfloat16* Wg = (t < 4) ? g_wq : (t < 8) ? g_wk : (t < 12) ? g_wv : g_wp;
    const char* base = (const char*)Wg + w * 16384 + (t & 3) * 128; // rows w*32.., cols (t&3)*64
    uint32_t stage = pw_u32 + (t % NSTAGE) * PW_STAGE_BYTES;
    #pragma unroll
    for (int c = 0; c < 8; ++c) {
        int idx = c * 32 + lane;
        int row = idx >> 3, j = idx & 7;
        asm volatile("cp.async.cg.shared.global [%0], [%1], 16;\n"
                     :: "r"(stage + row * 144 + j * 16), "l"(base + row * 512 + j * 16));
    }
    asm volatile("cp.async.commit_group;\n" ::: "memory");
}

// out(64 x 32slice) = A(64x256 smem) @ W_slice^T.  Barrier-free, warp-private stream.
__device__ __forceinline__ void gemm_slice(
    const __nv_bfloat16* __restrict__ A, const __nv_bfloat16* pwarp, uint32_t pw_u32,
    int gt0, int w, int lane, int g, int t4, float acc[4][4][4])
{
    #pragma unroll
    for (int kt = 0; kt < 4; ++kt) {
        int t = gt0 + kt;
        if (t == 15) { asm volatile("cp.async.wait_group 0;\n" ::: "memory"); }
        else         { asm volatile("cp.async.wait_group 1;\n" ::: "memory"); }
        __syncwarp();
        if (t + 2 < 16) issue_tile(t + 2, w, pw_u32, lane);
        const __nv_bfloat16* sW = pwarp + (t % NSTAGE) * PW_STAGE_ELEMS;
        #pragma unroll
        for (int ks = 0; ks < 4; ++ks) {
            int kc = kt * 64 + ks * 16 + t4 * 2;
            uint32_t a[4][4];
            #pragma unroll
            for (int mt = 0; mt < 4; ++mt) {
                int r = mt * 16 + g;
                a[mt][0] = *(const uint32_t*)(A + r * XS + kc);
                a[mt][1] = *(const uint32_t*)(A + (r + 8) * XS + kc);
                a[mt][2] = *(const uint32_t*)(A + r * XS + kc + 8);
                a[mt][3] = *(const uint32_t*)(A + (r + 8) * XS + kc + 8);
            }
            #pragma unroll
            for (int nt = 0; nt < 4; ++nt) {
                int rn = nt * 8 + g;
                int kk = ks * 16 + t4 * 2;
                uint32_t b0 = *(const uint32_t*)(sW + rn * WS + kk);
                uint32_t b1 = *(const uint32_t*)(sW + rn * WS + kk + 8);
                #pragma unroll
                for (int mt = 0; mt < 4; ++mt) mma16816(acc[mt][nt], a[mt], b0, b1);
            }
        }
    }
}

// V^T(32slice x 64tok) = Wv_slice(32x256) @ X^T.  A from private sW, B from sX rows.
__device__ __forceinline__ void vt_gemm(
    const __nv_bfloat16* __restrict__ sX, const __nv_bfloat16* pwarp, uint32_t pw_u32,
    int w, int lane, int g, int t4, float acc[2][8][4])
{
    #pragma unroll
    for (int kt = 0; kt < 4; ++kt) {
        int t = 8 + kt;
        asm volatile("cp.async.wait_group 1;\n" ::: "memory");
        __syncwarp();
        issue_tile(t + 2, w, pw_u32, lane);           // prefetch Wp during V/attention
        const __nv_bfloat16* sW = pwarp + (t % NSTAGE) * PW_STAGE_ELEMS;
        #pragma unroll
        for (int ks = 0; ks < 4; ++ks) {
            int kk = ks * 16 + t4 * 2;
            uint32_t a[2][4];
            #pragma unroll
            for (int mt = 0; mt < 2; ++mt) {
                int r = mt * 16 + g;
                a[mt][0] = *(const uint32_t*)(sW + r * WS + kk);
                a[mt][1] = *(const uint32_t*)(sW + (r + 8) * WS + kk);
                a[mt][2] = *(const uint32_t*)(sW + r * WS + kk + 8);
                a[mt][3] = *(const uint32_t*)(sW + (r + 8) * WS + kk + 8);
            }
            int kc = kt * 64 + ks * 16 + t4 * 2;
            #pragma unroll
            for (int nt = 0; nt < 8; ++nt) {
                int rtok = nt * 8 + g;
                uint32_t b0 = *(const uint32_t*)(sX + rtok * XS + kc);
                uint32_t b1 = *(const uint32_t*)(sX + rtok * XS + kc + 8);
                #pragma unroll
                for (int mt = 0; mt < 2; ++mt) mma16816(acc[mt][nt], a[mt], b0, b1);
            }
        }
    }
}

__global__ void __launch_bounds__(256, 1)
win_kernel(const float* __restrict__ inpt,
           const int* __restrict__ perm_n, const int* __restrict__ perm_t,
           const float* __restrict__ ln_g, const float* __restrict__ ln_b,
           const float* __restrict__ bq, const float* __restrict__ bk,
           const float* __restrict__ bv, const float* __restrict__ bp,
           float* __restrict__ out)
{
    extern __shared__ char smem[];
    __nv_bfloat16* sX = (__nv_bfloat16*)(smem + X_OFF);
    __nv_bfloat16* sO = (__nv_bfloat16*)(smem + O_OFF);
    float* sBias = (float*)(smem + BIAS_OFF);
    float* sG    = (float*)(smem + G_OFF);
    float* sBt   = (float*)(smem + BETA_OFF);
    int*   sAddr = (int*)(smem + ADDR_OFF);

    int tid = threadIdx.x;
    int wb = blockIdx.x;
    int tbi = wb & 63, nbi = (wb >> 6) & 7, b = wb >> 9;

    int w = tid >> 5, lane = tid & 31;
    int g = lane >> 2, t4 = lane & 3;

    const __nv_bfloat16* pwarp = (const __nv_bfloat16*)(smem + PW_OFF) + w * (NSTAGE * PW_STAGE_ELEMS);
    uint32_t pw_u32 = (uint32_t)__cvta_generic_to_shared(smem) + PW_OFF + w * (NSTAGE * PW_STAGE_BYTES);

    // start the private weight pipeline immediately (overlaps const staging + LN)
    issue_tile(0, w, pw_u32, lane);
    issue_tile(1, w, pw_u32, lane);

    // ---- stage constants + gather/scatter addresses ----
    sBias[tid]       = bq[tid];
    sBias[256 + tid] = bk[tid];
    sBias[512 + tid] = bv[tid];
    sBias[768 + tid] = bp[tid];
    sG[tid]  = ln_g[tid];
    sBt[tid] = ln_b[tid];
    if (tid < 64) {
        int fw = tid >> 3, tw = tid & 7;
        int pn = perm_n[b * NB_ + nbi * 8 + fw];
        int pt = perm_t[b * T_ + tbi * 8 + tw];
        sAddr[tid] = ((b * NB_ + pn) * T_ + pt) * C_;
    }
    __syncthreads();

    // ---- Phase 1: gather + LayerNorm -> sX (bf16) ----
    #pragma unroll
    for (int it = 0; it < 8; ++it) {
        int l = w * 8 + it;
        const float4* row = (const float4*)(inpt + sAddr[l]);
        float4 v0 = row[lane];
        float4 v1 = row[lane + 32];
        float s  = v0.x + v0.y + v0.z + v0.w + v1.x + v1.y + v1.z + v1.w;
        float sq = v0.x*v0.x + v0.y*v0.y + v0.z*v0.z + v0.w*v0.w
                 + v1.x*v1.x + v1.y*v1.y + v1.z*v1.z + v1.w*v1.w;
        #pragma unroll
        for (int o = 16; o; o >>= 1) {
            s  += __shfl_xor_sync(0xffffffffu, s, o);
            sq += __shfl_xor_sync(0xffffffffu, sq, o);
        }
        float mean = s * (1.0f / 256.0f);
        float var  = sq * (1.0f / 256.0f) - mean * mean;
        float rstd = rsqrtf(var + EPS_);
        int c0 = lane * 4, c1 = (lane + 32) * 4;
        uint32_t* xr = (uint32_t*)(sX + l * XS);
        float a0 = (v0.x - mean) * rstd * sG[c0]     + sBt[c0];
        float a1 = (v0.y - mean) * rstd * sG[c0 + 1] + sBt[c0 + 1];
        float a2 = (v0.z - mean) * rstd * sG[c0 + 2] + sBt[c0 + 2];
        float a3 = (v0.w - mean) * rstd * sG[c0 + 3] + sBt[c0 + 3];
        float b0v = (v1.x - mean) * rstd * sG[c1]     + sBt[c1];
        float b1v = (v1.y - mean) * rstd * sG[c1 + 1] + sBt[c1 + 1];
        float b2v = (v1.z - mean) * rstd * sG[c1 + 2] + sBt[c1 + 2];
        float b3v = (v1.w - mean) * rstd * sG[c1 + 3] + sBt[c1 + 3];
        xr[(c0 >> 1)]     = pack_bf16(a0, a1);
        xr[(c0 >> 1) + 1] = pack_bf16(a2, a3);
        xr[(c1 >> 1)]     = pack_bf16(b0v, b1v);
        xr[(c1 >> 1) + 1] = pack_bf16(b2v, b3v);
    }
    __syncthreads();

    // ---- Phase 2: warp w computes its head's Q, K, V^T — all register-resident ----
    uint32_t qf[4][4][2];   // Q[tok 64][dim 32] as C-frag packs
    uint32_t kf[4][4][2];   // K[tok 64][dim 32]
    uint32_t vf[2][8][2];   // V^T[dim 32][tok 64]

    {
        float acc[4][4][4];
        #pragma unroll
        for (int mt = 0; mt < 4; ++mt)
            #pragma unroll
            for (int nt = 0; nt < 4; ++nt)
                #pragma unroll
                for (int j = 0; j < 4; ++j) acc[mt][nt][j] = 0.f;
        gemm_slice(sX, pwarp, pw_u32, 0, w, lane, g, t4, acc);
        #pragma unroll
        for (int mt = 0; mt < 4; ++mt)
        #pragma unroll
        for (int nt = 0; nt < 4; ++nt) {
            int cn = w * 32 + nt * 8 + t4 * 2;
            float b0 = sBias[cn], b1 = sBias[cn + 1];
            qf[mt][nt][0] = pack_bf16((acc[mt][nt][0] + b0) * SCALE_, (acc[mt][nt][1] + b1) * SCALE_);
            qf[mt][nt][1] = pack_bf16((acc[mt][nt][2] + b0) * SCALE_, (acc[mt][nt][3] + b1) * SCALE_);
        }
    }
    {
        float acc[4][4][4];
        #pragma unroll
        for (int mt = 0; mt < 4; ++mt)
            #pragma unroll
            for (int nt = 0; nt < 4; ++nt)
                #pragma unroll
                for (int j = 0; j < 4; ++j) acc[mt][nt][j] = 0.f;
        gemm_slice(sX, pwarp, pw_u32, 4, w, lane, g, t4, acc);
        #pragma unroll
        for (int mt = 0; mt < 4; ++mt)
        #pragma unroll
        for (int nt = 0; nt < 4; ++nt) {
            int cn = w * 32 + nt * 8 + t4 * 2;
            float b0 = sBias[256 + cn], b1 = sBias[256 + cn + 1];
            kf[mt][nt][0] = pack_bf16(acc[mt][nt][0] + b0, acc[mt][nt][1] + b1);
            kf[mt][nt][1] = pack_bf16(acc[mt][nt][2] + b0, acc[mt][nt][3] + b1);
        }
    }
    {
        float accv[2][8][4];
        #pragma unroll
        for (int mt = 0; mt < 2; ++mt)
            #pragma unroll
            for (int nt = 0; nt < 8; ++nt)
                #pragma unroll
                for (int j = 0; j < 4; ++j) accv[mt][nt][j] = 0.f;
        vt_gemm(sX, pwarp, pw_u32, w, lane, g, t4, accv);
        #pragma unroll
        for (int mt = 0; mt < 2; ++mt) {
            float bg  = sBias[512 + w * 32 + mt * 16 + g];
            float bg8 = sBias[512 + w * 32 + mt * 16 + 8 + g];
            #pragma unroll
            for (int nt = 0; nt < 8; ++nt) {
                vf[mt][nt][0] = pack_bf16(accv[mt][nt][0] + bg,  accv[mt][nt][1] + bg);
                vf[mt][nt][1] = pack_bf16(accv[mt][nt][2] + bg8, accv[mt][nt][3] + bg8);
            }
        }
    }

    // ---- Phase 3: attention for head w, entirely in registers, two 32-row halves ----
    #pragma unroll
    for (int mh = 0; mh < 2; ++mh) {
        float s[2][8][4];
        #pragma unroll
        for (int mi = 0; mi < 2; ++mi)
            #pragma unroll
            for (int nt = 0; nt < 8; ++nt)
                #pragma unroll
                for (int j = 0; j < 4; ++j) s[mi][nt][j] = 0.f;

        #pragma unroll
        for (int kk = 0; kk < 2; ++kk) {
            uint32_t a[2][4];
            #pragma unroll
            for (int mi = 0; mi < 2; ++mi) {
                int ms = mh * 2 + mi;
                a[mi][0] = qf[ms][2 * kk][0];
                a[mi][1] = qf[ms][2 * kk][1];
                a[mi][2] = qf[ms][2 * kk + 1][0];
                a[mi][3] = qf[ms][2 * kk + 1][1];
            }
            #pragma unroll
            for (int nt = 0; nt < 8; ++nt) {
                uint32_t b0 = kf[nt >> 1][2 * kk][nt & 1];
                uint32_t b1 = kf[nt >> 1][2 * kk + 1][nt & 1];
                #pragma unroll
                for (int mi = 0; mi < 2; ++mi) mma16816(s[mi][nt], a[mi], b0, b1);
            }
        }

        // softmax over 64 cols per row (quad shares a row)
        #pragma unroll
        for (int mi = 0; mi < 2; ++mi)
        #pragma unroll
        for (int hf = 0; hf < 2; ++hf) {
            float m = -1e30f;
            #pragma unroll
            for (int nt = 0; nt < 8; ++nt)
                m = fmaxf(m, fmaxf(s[mi][nt][hf * 2], s[mi][nt][hf * 2 + 1]));
            m = fmaxf(m, __shfl_xor_sync(0xffffffffu, m, 1));
            m = fmaxf(m, __shfl_xor_sync(0xffffffffu, m, 2));
            float sum = 0.f;
            #pragma unroll
            for (int nt = 0; nt < 8; ++nt) {
                float e0 = __expf(s[mi][nt][hf * 2]     - m);
                float e1 = __expf(s[mi][nt][hf * 2 + 1] - m);
                s[mi][nt][hf * 2] = e0; s[mi][nt][hf * 2 + 1] = e1;
                sum += e0 + e1;
            }
            sum += __shfl_xor_sync(0xffffffffu, sum, 1);
            sum += __shfl_xor_sync(0xffffffffu, sum, 2);
            float inv = 1.0f / sum;
            #pragma unroll
            for (int nt = 0; nt < 8; ++nt) {
                s[mi][nt][hf * 2] *= inv; s[mi][nt][hf * 2 + 1] *= inv;
            }
        }

        // P C-frags -> A-frags
        uint32_t pA[2][4][4];
        #pragma unroll
        for (int mi = 0; mi < 2; ++mi)
        #pragma unroll
        for (int kt2 = 0; kt2 < 4; ++kt2) {
            pA[mi][kt2][0] = pack_bf16(s[mi][2 * kt2][0],     s[mi][2 * kt2][1]);
            pA[mi][kt2][1] = pack_bf16(s[mi][2 * kt2][2],     s[mi][2 * kt2][3]);
            pA[mi][kt2][2] = pack_bf16(s[mi][2 * kt2 + 1][0], s[mi][2 * kt2 + 1][1]);
            pA[mi][kt2][3] = pack_bf16(s[mi][2 * kt2 + 1][2], s[mi][2 * kt2 + 1][3]);
        }

        float o[2][4][4];
        #pragma unroll
        for (int mi = 0; mi < 2; ++mi)
            #pragma unroll
            for (int nt = 0; nt < 4; ++nt)
                #pragma unroll
                for (int j = 0; j < 4; ++j) o[mi][nt][j] = 0.f;

        #pragma unroll
        for (int kt2 = 0; kt2 < 4; ++kt2)
        #pragma unroll
        for (int nt = 0; nt < 4; ++nt) {
            uint32_t b0 = vf[nt >> 1][2 * kt2][nt & 1];
            uint32_t b1 = vf[nt >> 1][2 * kt2 + 1][nt & 1];
            #pragma unroll
            for (int mi = 0; mi < 2; ++mi) mma16816(o[mi][nt], pA[mi][kt2], b0, b1);
        }

        // write O (head w -> cols w*32..) into sO
        #pragma unroll
        for (int mi = 0; mi < 2; ++mi)
        #pragma unroll
        for (int nt = 0; nt < 4; ++nt) {
            int r = mh * 32 + mi * 16 + g;
            int cn = w * 32 + nt * 8 + t4 * 2;
            *(uint32_t*)(sO + r * XS + cn)       = pack_bf16(o[mi][nt][0], o[mi][nt][1]);
            *(uint32_t*)(sO + (r + 8) * XS + cn) = pack_bf16(o[mi][nt][2], o[mi][nt][3]);
        }
    }
    __syncthreads();   // all O columns materialized

    // ---- Phase 4: output projection + residual + scatter ----
    {
        float acc[4][4][4];
        #pragma unroll
        for (int mt = 0; mt < 4; ++mt)
            #pragma unroll
            for (int nt = 0; nt < 4; ++nt)
                #pragma unroll
                for (int j = 0; j < 4; ++j) acc[mt][nt][j] = 0.f;

        gemm_slice(sO, pwarp, pw_u32, 12, w, lane, g, t4, acc);

        #pragma unroll
        for (int mt = 0; mt < 4; ++mt)
        #pragma unroll
        for (int nt = 0; nt < 4; ++nt) {
            int r = mt * 16 + g, r2 = r + 8;
            int cn = w * 32 + nt * 8 + t4 * 2;
            float bb0 = sBias[768 + cn], bb1 = sBias[768 + cn + 1];
            int base1 = sAddr[r], base2 = sAddr[r2];
            float2 i0 = *(const float2*)(inpt + base1 + cn);
            float2 i1 = *(const float2*)(inpt + base2 + cn);
            float2 y0, y1;
            y0.x = acc[mt][nt][0] + bb0 + i0.x;
            y0.y = acc[mt][nt][1] + bb1 + i0.y;
            y1.x = acc[mt][nt][2] + bb0 + i1.x;
            y1.y = acc[mt][nt][3] + bb1 + i1.y;
            *(float2*)(out + base1 + cn) = y0;
            *(float2*)(out + base2 + cn) = y1;
        }
    }
}

extern "C" void kernel_launch(void* const* d_in, const int* in_sizes, int n_in,
                              void* d_out, int out_size) {
    const float* inpt   = (const float*)d_in[0];
    const int*   perm_n = (const int*)  d_in[1];
    const int*   perm_t = (const int*)  d_in[2];
    const float* ln_g   = (const float*)d_in[3];
    const float* ln_b   = (const float*)d_in[4];
    const float* Wq     = (const float*)d_in[5];
    const float* bq     = (const float*)d_in[6];
    const float* Wk     = (const float*)d_in[7];
    const float* bk     = (const float*)d_in[8];
    const float* Wv     = (const float*)d_in[9];
    const float* bv     = (const float*)d_in[10];
    const float* Wp     = (const float*)d_in[11];
    const float* bp     = (const float*)d_in[12];
    float* out = (float*)d_out;

    cudaFuncSetAttribute(win_kernel, cudaFuncAttributeMaxDynamicSharedMemorySize, SMEM_TOTAL);

    cvt_kernel<<<256, 256>>>(Wq, Wk, Wv, Wp);
    win_kernel<<<NWIN, 256, SMEM_TOTAL>>>(inpt, perm_n, perm_t, ln_g, ln_b,
                                          bq, bk, bv, bp, out);
}